// round 16
// baseline (speedup 1.0000x reference)
#include <cuda_runtime.h>
#include <cuda_fp16.h>
#include <cuda_bf16.h>
#include <cstdint>

// B=4096 scenes, L=200 padded, V=50000, H=128.
// out[i,h] = b[h] + sum_{j<len_i} W[h, tokens[i,j]]
// R14/R15: test the L1tex-MSHR-wall theory with cp.async.cg (LDGSTS): no
// depth cap, no dest registers -> outstanding bytes bounded by smem (16KB per
// block in flight), not miss-tracking slots. Double-buffered 64-row smem
// stages, commit_group/wait_group pipeline, LDS consume with chain-4 HADD2.
// (R15 = R14 + missing <cstdint> include.)

#define B_N 4096
#define L_N 200
#define V_N 50000
#define H_N 128

#define ROWS_PER_CHUNK 64
#define ROW_BYTES 256
#define STAGE_BYTES (ROWS_PER_CHUNK * ROW_BYTES)   // 16 KB

__device__ __align__(256) __half g_Wt[(size_t)V_N * H_N];   // 12.8 MB, [V,H]

// ---------------------------------------------------------------------------
// Transpose+convert: W[H,V] fp32 -> g_Wt[V,H] fp16 (R12 version, known-good).
// ---------------------------------------------------------------------------
__global__ void __launch_bounds__(256) transpose_W_kernel(const float* __restrict__ W) {
    __shared__ float s[32][132];
    int v0   = blockIdx.x * 32;
    int w    = threadIdx.x >> 5;
    int lane = threadIdx.x & 31;

    int v = v0 + lane;
    bool vok = (v < V_N);
    #pragma unroll
    for (int i = 0; i < 16; i++) {
        int h = i * 8 + w;
        s[lane][h] = vok ? W[(size_t)h * V_N + v] : 0.f;
    }
    __syncthreads();

    #pragma unroll
    for (int i = 0; i < 4; i++) {
        int vr = i * 8 + w;
        int vg = v0 + vr;
        if (vg < V_N) {
            float4 f = *reinterpret_cast<const float4*>(&s[vr][4 * lane]);
            __half2 lo = __floats2half2_rn(f.x, f.y);
            __half2 hi = __floats2half2_rn(f.z, f.w);
            uint2 val;
            val.x = *reinterpret_cast<unsigned*>(&lo);
            val.y = *reinterpret_cast<unsigned*>(&hi);
            *reinterpret_cast<uint2*>(&g_Wt[(size_t)vg * H_N + 4 * lane]) = val;
        }
    }
}

// ---------------------------------------------------------------------------
__device__ __forceinline__ uint32_t smem_u32(const void* p) {
    uint32_t a;
    asm("{ .reg .u64 t; cvta.to.shared.u64 t, %1; cvt.u32.u64 %0, t; }"
        : "=r"(a) : "l"(p));
    return a;
}

// ---------------------------------------------------------------------------
// Gather via cp.async.cg: one block (128 thr) per scene.
// Producers: all threads, 8 x 16B cp.async per thread per 64-row chunk.
// Consumers: warp w reduces rows [16w,16w+16) of the arrived stage from smem.
// Lane owns h = 4*lane..4*lane+3 (uint2); chain-4 HADD2 -> fp32.
// ---------------------------------------------------------------------------
__global__ void __launch_bounds__(128) bow_cpasync_kernel(
    const int* __restrict__ tokens,
    const int* __restrict__ lengths,
    const float* __restrict__ bias,
    float* __restrict__ out)
{
    __shared__ __align__(16) unsigned char stage[2][STAGE_BYTES];
    __shared__ int    s_tok[L_N];
    __shared__ float4 shp[3][32];

    int scene = blockIdx.x;
    int tid   = threadIdx.x;
    int wid   = tid >> 5;
    int lane  = tid & 31;

    int len = lengths[scene];
    for (int i = tid; i < L_N; i += 128)
        s_tok[i] = tokens[(size_t)scene * L_N + i];
    __syncthreads();

    int nchunk = (len + ROWS_PER_CHUNK - 1) / ROWS_PER_CHUNK;
    const char* WtB = reinterpret_cast<const char*>(g_Wt);
    uint32_t stA[2] = { smem_u32(&stage[0][0]), smem_u32(&stage[1][0]) };

    // Issue one chunk's copies + commit a group (all threads, uniform).
    auto issue_chunk = [&](int c) {
        int base = c * ROWS_PER_CHUNK;
        int rows = len - base;
        if (rows > ROWS_PER_CHUNK) rows = ROWS_PER_CHUNK;
        uint32_t dstBase = stA[c & 1];
        #pragma unroll
        for (int i = 0; i < 8; i++) {
            int n = i * 128 + tid;          // 0..1023 -> (row, 16B slice)
            int row = n >> 4;
            if (row < rows) {
                int t = s_tok[base + row];
                uint32_t dst = dstBase + (uint32_t)n * 16u;
                const char* src = WtB + (size_t)(unsigned)t * 256u + (n & 15) * 16;
                asm volatile("cp.async.cg.shared.global [%0], [%1], 16;"
                             :: "r"(dst), "l"(src) : "memory");
            }
        }
        asm volatile("cp.async.commit_group;" ::: "memory");
    };

    if (nchunk > 0) issue_chunk(0);
    if (nchunk > 1) issue_chunk(1);

    float4 acc = make_float4(0.f, 0.f, 0.f, 0.f);

    for (int c = 0; c < nchunk; c++) {
        if (c + 1 < nchunk)
            asm volatile("cp.async.wait_group 1;" ::: "memory");
        else
            asm volatile("cp.async.wait_group 0;" ::: "memory");
        __syncthreads();   // everyone's copies for chunk c have landed

        int base = c * ROWS_PER_CHUNK;
        int rows = len - base;
        if (rows > ROWS_PER_CHUNK) rows = ROWS_PER_CHUNK;

        const unsigned char* st = stage[c & 1];
        int r  = wid * 16;
        int r1 = r + 16;
        if (r1 > rows) r1 = rows;

        // Chains of 4 rows in fp16, flushed to fp32.
        for (; r + 4 <= r1; r += 4) {
            uint2 w0 = *reinterpret_cast<const uint2*>(st + (r + 0) * ROW_BYTES + lane * 8);
            uint2 w1 = *reinterpret_cast<const uint2*>(st + (r + 1) * ROW_BYTES + lane * 8);
            uint2 w2 = *reinterpret_cast<const uint2*>(st + (r + 2) * ROW_BYTES + lane * 8);
            uint2 w3 = *reinterpret_cast<const uint2*>(st + (r + 3) * ROW_BYTES + lane * 8);
            __half2 a0 = __hadd2(__hadd2(*reinterpret_cast<__half2*>(&w0.x),
                                         *reinterpret_cast<__half2*>(&w1.x)),
                                 __hadd2(*reinterpret_cast<__half2*>(&w2.x),
                                         *reinterpret_cast<__half2*>(&w3.x)));
            __half2 a1 = __hadd2(__hadd2(*reinterpret_cast<__half2*>(&w0.y),
                                         *reinterpret_cast<__half2*>(&w1.y)),
                                 __hadd2(*reinterpret_cast<__half2*>(&w2.y),
                                         *reinterpret_cast<__half2*>(&w3.y)));
            float2 f01 = __half22float2(a0);
            float2 f23 = __half22float2(a1);
            acc.x += f01.x; acc.y += f01.y;
            acc.z += f23.x; acc.w += f23.y;
        }
        for (; r < r1; r++) {
            uint2 w = *reinterpret_cast<const uint2*>(st + r * ROW_BYTES + lane * 8);
            float2 f01 = __half22float2(*reinterpret_cast<__half2*>(&w.x));
            float2 f23 = __half22float2(*reinterpret_cast<__half2*>(&w.y));
            acc.x += f01.x; acc.y += f01.y;
            acc.z += f23.x; acc.w += f23.y;
        }

        __syncthreads();   // stage free for reuse
        if (c + 2 < nchunk) issue_chunk(c + 2);
    }

    // Block reduce: warps 1-3 -> smem, warp 0 combines + bias + store.
    if (wid != 0) shp[wid - 1][lane] = acc;
    __syncthreads();
    if (wid == 0) {
        float4 b4 = reinterpret_cast<const float4*>(bias)[lane];
        #pragma unroll
        for (int w = 0; w < 3; w++) {
            float4 p = shp[w][lane];
            acc.x += p.x; acc.y += p.y; acc.z += p.z; acc.w += p.w;
        }
        acc.x += b4.x; acc.y += b4.y; acc.z += b4.z; acc.w += b4.w;
        reinterpret_cast<float4*>(out + (size_t)scene * H_N)[lane] = acc;
    }
}

// ---------------------------------------------------------------------------
extern "C" void kernel_launch(void* const* d_in, const int* in_sizes, int n_in,
                              void* d_out, int out_size) {
    const int*   tokens  = (const int*)d_in[0];
    const int*   lengths = (const int*)d_in[1];
    const float* W       = (const float*)d_in[2];
    const float* bias    = (const float*)d_in[3];
    float*       out     = (float*)d_out;

    (void)in_sizes; (void)n_in; (void)out_size;

    transpose_W_kernel<<<(V_N + 31) / 32, 256>>>(W);
    bow_cpasync_kernel<<<B_N, 128>>>(tokens, lengths, bias, out);
}